// round 10
// baseline (speedup 1.0000x reference)
#include <cuda_runtime.h>

#define TT 512
#define BB 16384
#define HH 32
#define RL 4              // batch lanes per thread
#define BLK 256
#define LPC 256           // lanes per CTA = (BLK/4) * RL
#define AST 36            // floats per act row (16B aligned; 36 ≡ 4 mod 32 banks)

typedef unsigned long long u64;

// ---- packed f32x2 helpers (PTX-only; ptxas never auto-fuses) ----
__device__ __forceinline__ u64 fma2(u64 a, u64 b, u64 c) {
    u64 d; asm("fma.rn.f32x2 %0,%1,%2,%3;" : "=l"(d) : "l"(a), "l"(b), "l"(c)); return d;
}
__device__ __forceinline__ u64 mul2(u64 a, u64 b) {
    u64 d; asm("mul.rn.f32x2 %0,%1,%2;" : "=l"(d) : "l"(a), "l"(b)); return d;
}
__device__ __forceinline__ u64 pack2(float lo, float hi) {
    u64 r; asm("mov.b64 %0,{%1,%2};" : "=l"(r) : "f"(lo), "f"(hi)); return r;
}
__device__ __forceinline__ u64 dup2(float x) { return pack2(x, x); }
__device__ __forceinline__ void unpack2(u64 v, float& lo, float& hi) {
    asm("mov.b64 {%0,%1},%2;" : "=f"(lo), "=f"(hi) : "l"(v));
}

// stable softplus + sigmoid sharing one exp
__device__ __forceinline__ void sp_sig(float z, float& sp, float& sg) {
    float u = __expf(-fabsf(z));
    float d = 1.0f + u;
    float r = __fdividef(1.0f, d);
    sp = fmaxf(z, 0.0f) + __logf(d);
    sg = (z >= 0.0f) ? r : 1.0f - r;
}
__device__ __forceinline__ float sigf(float z) {
    float u = __expf(-fabsf(z));
    float r = __fdividef(1.0f, 1.0f + u);
    return (z >= 0.0f) ? r : 1.0f - r;
}

__global__ void __launch_bounds__(BLK, 1) rnncell_2w_kernel(
    const float* __restrict__ eps, const float* __restrict__ hs,
    const float* __restrict__ W1,  const float* __restrict__ b1,
    const float* __restrict__ W2,  const float* __restrict__ b2,
    const float* __restrict__ W3,  float* __restrict__ out)
{
    __shared__ __align__(16) float sW2 [HH * HH];     // W2[k][j]
    __shared__ __align__(16) float sW2T[HH * HH];     // W2T[j][k]
    __shared__ __align__(16) float sAct[LPC * AST];   // per-lane activation rows

    const int tid = threadIdx.x;
    for (int i = tid; i < HH * HH; i += BLK) {
        float w = W2[i];
        sW2[i] = w;
        sW2T[(i & 31) * HH + (i >> 5)] = w;
    }
    __syncthreads();

    const int quarter = tid & 3;      // 8-unit chunk I own
    const int grp     = tid >> 2;     // group 0..63
    const int co      = quarter * 8;

    // 4 consecutive gids per thread -> vector LDG/STG
    const int gbase = blockIdx.x * LPC + grp * RL;

    // act row for lane (grp,r) = grp + 64*r: rows spaced 36 floats -> banks
    // 4*grp, all distinct within the 8 grps of a warp, 4-way quarter-broadcast
    // => conflict-free act loads (same layout law as R7, 64 groups).
    float* act[RL];
    #pragma unroll
    for (int r = 0; r < RL; ++r) act[r] = sAct + (grp + 64 * r) * AST;

    // loop-invariant per-chunk weights
    u64 w1ap[4], w1bp[4], b1p[4], b2p[4];
    float w3s[8];
    #pragma unroll
    for (int j = 0; j < 4; ++j) {
        w1ap[j] = pack2(W1[co + 2*j],      W1[co + 2*j + 1]);
        w1bp[j] = pack2(W1[HH + co + 2*j], W1[HH + co + 2*j + 1]);
        b1p [j] = pack2(b1[co + 2*j],      b1[co + 2*j + 1]);
        b2p [j] = pack2(b2[co + 2*j],      b2[co + 2*j + 1]);
    }
    #pragma unroll
    for (int j = 0; j < 8; ++j) w3s[j] = W3[co + j];

    float gam[RL], ec[RL], hc[RL];
    {
        float4 e4 = *(const float4*)(eps + gbase);
        float4 h4 = *(const float4*)(hs  + gbase);
        ec[0]=e4.x; ec[1]=e4.y; ec[2]=e4.z; ec[3]=e4.w;
        hc[0]=h4.x; hc[1]=h4.y; hc[2]=h4.z; hc[3]=h4.w;
        #pragma unroll
        for (int r = 0; r < RL; ++r) gam[r] = 0.0f;
    }

    for (int t = 0; t < TT; ++t) {
        const int tn = (t + 1 < TT) ? t + 1 : t;
        float4 en4 = *(const float4*)(eps + (size_t)tn * BB + gbase);
        float4 hn4 = *(const float4*)(hs  + (size_t)tn * BB + gbase);

        // ---- layer 1 (my 8 units x 4 lanes): z1 -> softplus (staged), sigmoid (regs)
        u64 s1p[RL][4];
        #pragma unroll
        for (int r = 0; r < RL; ++r) {
            const u64 e2 = dup2(ec[r]);
            const u64 g2 = dup2(gam[r]);
            float a1v[8];
            #pragma unroll
            for (int j = 0; j < 4; ++j) {
                u64 z = fma2(e2, w1ap[j], fma2(g2, w1bp[j], b1p[j]));
                float za, zb; unpack2(z, za, zb);
                float spa, sga, spb, sgb;
                sp_sig(za, spa, sga);
                sp_sig(zb, spb, sgb);
                a1v[2*j]   = spa;
                a1v[2*j+1] = spb;
                s1p[r][j]  = pack2(sga, sgb);
            }
            *(float4*)(act[r] + co)     = make_float4(a1v[0], a1v[1], a1v[2], a1v[3]);
            *(float4*)(act[r] + co + 4) = make_float4(a1v[4], a1v[5], a1v[6], a1v[7]);
        }
        __syncwarp();

        // ---- matvec1: z2[my 8 cols] = b2 + sum_k a1[k] * W2[k][.] ----
        u64 acc[RL][4];
        #pragma unroll
        for (int r = 0; r < RL; ++r)
            #pragma unroll
            for (int j = 0; j < 4; ++j) acc[r][j] = b2p[j];

        #pragma unroll
        for (int q = 0; q < 4; ++q) {
            float av[RL][8];
            #pragma unroll
            for (int r = 0; r < RL; ++r) {
                float4 lo = *(const float4*)(act[r] + q * 8);
                float4 hi = *(const float4*)(act[r] + q * 8 + 4);
                av[r][0]=lo.x; av[r][1]=lo.y; av[r][2]=lo.z; av[r][3]=lo.w;
                av[r][4]=hi.x; av[r][5]=hi.y; av[r][6]=hi.z; av[r][7]=hi.w;
            }
            #pragma unroll
            for (int kk = 0; kk < 8; ++kk) {
                const float* wr = sW2 + (q * 8 + kk) * HH + co;
                ulonglong2 wlo = *(const ulonglong2*)wr;
                ulonglong2 whi = *(const ulonglong2*)(wr + 4);
                #pragma unroll
                for (int r = 0; r < RL; ++r) {
                    u64 ak = dup2(av[r][kk]);
                    acc[r][0] = fma2(ak, wlo.x, acc[r][0]);
                    acc[r][1] = fma2(ak, wlo.y, acc[r][1]);
                    acc[r][2] = fma2(ak, whi.x, acc[r][2]);
                    acc[r][3] = fma2(ak, whi.y, acc[r][3]);
                }
            }
        }
        __syncwarp();

        // ---- v2 = sigmoid(z2) * W3, staged ----
        #pragma unroll
        for (int r = 0; r < RL; ++r) {
            float v2v[8];
            #pragma unroll
            for (int j = 0; j < 4; ++j) {
                float za, zb; unpack2(acc[r][j], za, zb);
                v2v[2*j]   = sigf(za) * w3s[2*j];
                v2v[2*j+1] = sigf(zb) * w3s[2*j+1];
            }
            *(float4*)(act[r] + co)     = make_float4(v2v[0], v2v[1], v2v[2], v2v[3]);
            *(float4*)(act[r] + co + 4) = make_float4(v2v[4], v2v[5], v2v[6], v2v[7]);
        }
        __syncwarp();

        // ---- matvec2: t[my 8 rows] = sum_j v2[j] * W2T[j][.] ----
        u64 tacc[RL][4];
        #pragma unroll
        for (int r = 0; r < RL; ++r)
            #pragma unroll
            for (int j = 0; j < 4; ++j) tacc[r][j] = 0ull;

        #pragma unroll
        for (int q = 0; q < 4; ++q) {
            float vv[RL][8];
            #pragma unroll
            for (int r = 0; r < RL; ++r) {
                float4 lo = *(const float4*)(act[r] + q * 8);
                float4 hi = *(const float4*)(act[r] + q * 8 + 4);
                vv[r][0]=lo.x; vv[r][1]=lo.y; vv[r][2]=lo.z; vv[r][3]=lo.w;
                vv[r][4]=hi.x; vv[r][5]=hi.y; vv[r][6]=hi.z; vv[r][7]=hi.w;
            }
            #pragma unroll
            for (int kk = 0; kk < 8; ++kk) {
                const float* wr = sW2T + (q * 8 + kk) * HH + co;
                ulonglong2 wlo = *(const ulonglong2*)wr;
                ulonglong2 whi = *(const ulonglong2*)(wr + 4);
                #pragma unroll
                for (int r = 0; r < RL; ++r) {
                    u64 vk = dup2(vv[r][kk]);
                    tacc[r][0] = fma2(vk, wlo.x, tacc[r][0]);
                    tacc[r][1] = fma2(vk, wlo.y, tacc[r][1]);
                    tacc[r][2] = fma2(vk, whi.x, tacc[r][2]);
                    tacc[r][3] = fma2(vk, whi.y, tacc[r][3]);
                }
            }
        }
        __syncwarp();

        // ---- v1 = sig1 .* t ; partial dots ; 4-thread butterfly ----
        float g0[RL], g1[RL];
        #pragma unroll
        for (int r = 0; r < RL; ++r) {
            u64 g0p = 0ull, g1p = 0ull;
            #pragma unroll
            for (int j = 0; j < 4; ++j) {
                u64 v1 = mul2(s1p[r][j], tacc[r][j]);
                g0p = fma2(v1, w1ap[j], g0p);
                g1p = fma2(v1, w1bp[j], g1p);
            }
            float a, b;
            unpack2(g0p, a, b); g0[r] = a + b;
            unpack2(g1p, a, b); g1[r] = a + b;
        }
        #pragma unroll
        for (int r = 0; r < RL; ++r) {
            g0[r] += __shfl_xor_sync(0xffffffffu, g0[r], 1);
            g0[r] += __shfl_xor_sync(0xffffffffu, g0[r], 2);
            g1[r] += __shfl_xor_sync(0xffffffffu, g1[r], 1);
            g1[r] += __shfl_xor_sync(0xffffffffu, g1[r], 2);
        }

        if (quarter == 0)
            *(float4*)(out + (size_t)t * BB + gbase) =
                make_float4(g0[0], g0[1], g0[2], g0[3]);

        gam[0] = fmaf(hc[0], -g1[0], gam[0]);
        gam[1] = fmaf(hc[1], -g1[1], gam[1]);
        gam[2] = fmaf(hc[2], -g1[2], gam[2]);
        gam[3] = fmaf(hc[3], -g1[3], gam[3]);

        ec[0]=en4.x; ec[1]=en4.y; ec[2]=en4.z; ec[3]=en4.w;
        hc[0]=hn4.x; hc[1]=hn4.y; hc[2]=hn4.z; hc[3]=hn4.w;
    }
}

extern "C" void kernel_launch(void* const* d_in, const int* in_sizes, int n_in,
                              void* d_out, int out_size) {
    const float* eps = (const float*)d_in[0];
    const float* hs  = (const float*)d_in[1];
    const float* W1  = (const float*)d_in[2];
    const float* b1  = (const float*)d_in[3];
    const float* W2  = (const float*)d_in[4];
    const float* b2  = (const float*)d_in[5];
    const float* W3  = (const float*)d_in[6];
    float* out = (float*)d_out;

    // 16384 lanes / 256 per CTA = 64 CTAs x 256 threads -> 2 warps/SMSP,
    // per-thread structure identical to R7 (RL=4 amortization preserved)
    rnncell_2w_kernel<<<BB / LPC, BLK>>>(eps, hs, W1, b1, W2, b2, W3, out);
}

// round 11
// speedup vs baseline: 1.7079x; 1.7079x over previous
#include <cuda_runtime.h>

#define TT 512
#define BB 16384
#define HH 32
#define RL 4              // batch lanes per thread
#define BLK 256
#define LPC 128           // lanes per CTA; 8 threads per lane (4 quarters x 2 k-halves)
#define AST 36            // act row stride (floats)
#define WST 36            // weight row stride (floats)
#define WHALF (16*WST+4)  // offset of k-half 1 rows (4-float shift kills q x h bank collisions)

typedef unsigned long long u64;

// ---- packed f32x2 helpers (PTX-only; ptxas never auto-fuses) ----
__device__ __forceinline__ u64 fma2(u64 a, u64 b, u64 c) {
    u64 d; asm("fma.rn.f32x2 %0,%1,%2,%3;" : "=l"(d) : "l"(a), "l"(b), "l"(c)); return d;
}
__device__ __forceinline__ u64 mul2(u64 a, u64 b) {
    u64 d; asm("mul.rn.f32x2 %0,%1,%2;" : "=l"(d) : "l"(a), "l"(b)); return d;
}
__device__ __forceinline__ u64 add2(u64 a, u64 b) {
    u64 d; asm("add.rn.f32x2 %0,%1,%2;" : "=l"(d) : "l"(a), "l"(b)); return d;
}
__device__ __forceinline__ u64 pack2(float lo, float hi) {
    u64 r; asm("mov.b64 %0,{%1,%2};" : "=l"(r) : "f"(lo), "f"(hi)); return r;
}
__device__ __forceinline__ u64 dup2(float x) { return pack2(x, x); }
__device__ __forceinline__ void unpack2(u64 v, float& lo, float& hi) {
    asm("mov.b64 {%0,%1},%2;" : "=f"(lo), "=f"(hi) : "l"(v));
}
__device__ __forceinline__ u64 shfl_xor64(u64 v, int m) {
    return (u64)__shfl_xor_sync(0xffffffffu, (long long)v, m);
}

// stable softplus + sigmoid sharing one exp
__device__ __forceinline__ void sp_sig(float z, float& sp, float& sg) {
    float u = __expf(-fabsf(z));
    float d = 1.0f + u;
    float r = __fdividef(1.0f, d);
    sp = fmaxf(z, 0.0f) + __logf(d);
    sg = (z >= 0.0f) ? r : 1.0f - r;
}
__device__ __forceinline__ float sigf(float z) {
    float u = __expf(-fabsf(z));
    float r = __fdividef(1.0f, 1.0f + u);
    return (z >= 0.0f) ? r : 1.0f - r;
}

__global__ void __launch_bounds__(BLK, 1) rnncell_sk_kernel(
    const float* __restrict__ eps, const float* __restrict__ hs,
    const float* __restrict__ W1,  const float* __restrict__ b1,
    const float* __restrict__ W2,  const float* __restrict__ b2,
    const float* __restrict__ W3,  float* __restrict__ out)
{
    // weight rows padded to 36 floats; half-1 rows shifted +4 floats
    __shared__ __align__(16) float sW2 [2 * WHALF + 64];   // W2[k][j]
    __shared__ __align__(16) float sW2T[2 * WHALF + 64];   // W2T[j][k]
    __shared__ __align__(16) float sAct[LPC * AST];        // per-lane activation rows

    const int tid = threadIdx.x;
    for (int i = tid; i < HH * HH; i += BLK) {
        const int k = i >> 5, j = i & 31;
        const float w = W2[i];
        sW2 [k * WST + ((k >> 4) << 2) + j] = w;   // row k, col j
        sW2T[j * WST + ((j >> 4) << 2) + k] = w;   // row j, col k
    }
    __syncthreads();

    const int q   = tid & 3;          // output-chunk quarter (8 units)
    const int h   = (tid >> 2) & 1;   // k-half
    const int grp = tid >> 3;         // group 0..31, serves 4 lanes
    const int co  = q * 8;            // 8-col/row block base
    const int uo  = co + h * 4;       // my 4 units (L1 / V2 / epilogue)
    const int ko  = h * 16;           // my k half [ko, ko+16)

    const float* sW2h  = sW2  + h * WHALF;   // my 16 weight rows (MV1)
    const float* sW2Th = sW2T + h * WHALF;   // my 16 weight rows (MV2)

    const int gbase = blockIdx.x * LPC + grp * RL;   // 4 consecutive gids

    float* act[RL];
    #pragma unroll
    for (int r = 0; r < RL; ++r) act[r] = sAct + (grp + 32 * r) * AST;

    // per-thread weights: my 4 units scalar + packed
    float w1a4[4], w1b4[4], b14[4], w34[4];
    #pragma unroll
    for (int j = 0; j < 4; ++j) {
        w1a4[j] = W1[uo + j];
        w1b4[j] = W1[HH + uo + j];
        b14 [j] = b1[uo + j];
        w34 [j] = W3[uo + j];
    }
    u64 w1apk[2], w1bpk[2];
    #pragma unroll
    for (int j = 0; j < 2; ++j) {
        w1apk[j] = pack2(w1a4[2*j], w1a4[2*j + 1]);
        w1bpk[j] = pack2(w1b4[2*j], w1b4[2*j + 1]);
    }
    // b2 for my 8 cols; only the h==0 partial carries the bias
    u64 b2pk[4];
    #pragma unroll
    for (int j = 0; j < 4; ++j)
        b2pk[j] = h ? 0ull : pack2(b2[co + 2*j], b2[co + 2*j + 1]);

    float gam[RL], ec[RL], hc[RL];
    {
        float4 e4 = *(const float4*)(eps + gbase);
        float4 h4 = *(const float4*)(hs  + gbase);
        ec[0]=e4.x; ec[1]=e4.y; ec[2]=e4.z; ec[3]=e4.w;
        hc[0]=h4.x; hc[1]=h4.y; hc[2]=h4.z; hc[3]=h4.w;
        #pragma unroll
        for (int r = 0; r < RL; ++r) gam[r] = 0.0f;
    }

    for (int t = 0; t < TT; ++t) {
        const int tn = (t + 1 < TT) ? t + 1 : t;
        float4 en4 = *(const float4*)(eps + (size_t)tn * BB + gbase);
        float4 hn4 = *(const float4*)(hs  + (size_t)tn * BB + gbase);

        // ---- layer 1: my 4 units x 4 lanes -> softplus staged, sigmoid kept ----
        u64 s1p[RL][2];
        #pragma unroll
        for (int r = 0; r < RL; ++r) {
            float a1v[4], sgv[4];
            #pragma unroll
            for (int j = 0; j < 4; ++j) {
                float z = fmaf(ec[r], w1a4[j], fmaf(gam[r], w1b4[j], b14[j]));
                sp_sig(z, a1v[j], sgv[j]);
            }
            s1p[r][0] = pack2(sgv[0], sgv[1]);
            s1p[r][1] = pack2(sgv[2], sgv[3]);
            *(float4*)(act[r] + uo) = make_float4(a1v[0], a1v[1], a1v[2], a1v[3]);
        }
        __syncwarp();

        // ---- MV1 partial: cols [co,co+8), k in [ko,ko+16) ----
        u64 acc[RL][4];
        #pragma unroll
        for (int r = 0; r < RL; ++r)
            #pragma unroll
            for (int j = 0; j < 4; ++j) acc[r][j] = b2pk[j];

        #pragma unroll
        for (int kb = 0; kb < 2; ++kb) {
            float av[RL][8];
            #pragma unroll
            for (int r = 0; r < RL; ++r) {
                float4 lo = *(const float4*)(act[r] + ko + kb * 8);
                float4 hi = *(const float4*)(act[r] + ko + kb * 8 + 4);
                av[r][0]=lo.x; av[r][1]=lo.y; av[r][2]=lo.z; av[r][3]=lo.w;
                av[r][4]=hi.x; av[r][5]=hi.y; av[r][6]=hi.z; av[r][7]=hi.w;
            }
            #pragma unroll
            for (int kk = 0; kk < 8; ++kk) {
                const float* wr = sW2h + (kb * 8 + kk) * WST + co;
                ulonglong2 wlo = *(const ulonglong2*)wr;
                ulonglong2 whi = *(const ulonglong2*)(wr + 4);
                #pragma unroll
                for (int r = 0; r < RL; ++r) {
                    u64 ak = dup2(av[r][kk]);
                    acc[r][0] = fma2(ak, wlo.x, acc[r][0]);
                    acc[r][1] = fma2(ak, wlo.y, acc[r][1]);
                    acc[r][2] = fma2(ak, whi.x, acc[r][2]);
                    acc[r][3] = fma2(ak, whi.y, acc[r][3]);
                }
            }
        }
        // combine with k-half partner (xor 4): I need full sums only for MY
        // col-pairs (2h,2h+1); partner sends its partial for those.
        u64 accf[RL][2];
        #pragma unroll
        for (int r = 0; r < RL; ++r) {
            u64 mine0 = h ? acc[r][2] : acc[r][0];
            u64 mine1 = h ? acc[r][3] : acc[r][1];
            u64 send0 = h ? acc[r][0] : acc[r][2];
            u64 send1 = h ? acc[r][1] : acc[r][3];
            accf[r][0] = add2(mine0, shfl_xor64(send0, 4));
            accf[r][1] = add2(mine1, shfl_xor64(send1, 4));
        }
        __syncwarp();   // all MV1 act reads done before V2 overwrites

        // ---- V2: my 4 cols, sigmoid * W3, staged ----
        #pragma unroll
        for (int r = 0; r < RL; ++r) {
            float za, zb, zc, zd;
            unpack2(accf[r][0], za, zb);
            unpack2(accf[r][1], zc, zd);
            *(float4*)(act[r] + uo) = make_float4(
                sigf(za) * w34[0], sigf(zb) * w34[1],
                sigf(zc) * w34[2], sigf(zd) * w34[3]);
        }
        __syncwarp();

        // ---- MV2 partial: rows [co,co+8), j in [ko,ko+16) ----
        u64 tacc[RL][4];
        #pragma unroll
        for (int r = 0; r < RL; ++r)
            #pragma unroll
            for (int j = 0; j < 4; ++j) tacc[r][j] = 0ull;

        #pragma unroll
        for (int kb = 0; kb < 2; ++kb) {
            float vv[RL][8];
            #pragma unroll
            for (int r = 0; r < RL; ++r) {
                float4 lo = *(const float4*)(act[r] + ko + kb * 8);
                float4 hi = *(const float4*)(act[r] + ko + kb * 8 + 4);
                vv[r][0]=lo.x; vv[r][1]=lo.y; vv[r][2]=lo.z; vv[r][3]=lo.w;
                vv[r][4]=hi.x; vv[r][5]=hi.y; vv[r][6]=hi.z; vv[r][7]=hi.w;
            }
            #pragma unroll
            for (int kk = 0; kk < 8; ++kk) {
                const float* wr = sW2Th + (kb * 8 + kk) * WST + co;
                ulonglong2 wlo = *(const ulonglong2*)wr;
                ulonglong2 whi = *(const ulonglong2*)(wr + 4);
                #pragma unroll
                for (int r = 0; r < RL; ++r) {
                    u64 vk = dup2(vv[r][kk]);
                    tacc[r][0] = fma2(vk, wlo.x, tacc[r][0]);
                    tacc[r][1] = fma2(vk, wlo.y, tacc[r][1]);
                    tacc[r][2] = fma2(vk, whi.x, tacc[r][2]);
                    tacc[r][3] = fma2(vk, whi.y, tacc[r][3]);
                }
            }
        }
        // combine: full t for MY row-pairs (2h,2h+1)
        u64 tf[RL][2];
        #pragma unroll
        for (int r = 0; r < RL; ++r) {
            u64 mine0 = h ? tacc[r][2] : tacc[r][0];
            u64 mine1 = h ? tacc[r][3] : tacc[r][1];
            u64 send0 = h ? tacc[r][0] : tacc[r][2];
            u64 send1 = h ? tacc[r][1] : tacc[r][3];
            tf[r][0] = add2(mine0, shfl_xor64(send0, 4));
            tf[r][1] = add2(mine1, shfl_xor64(send1, 4));
        }
        __syncwarp();   // MV2 act reads done before next iteration's L1 stores

        // ---- epilogue: v1 = sig1 .* t over my 4 rows; dots; 8-thread butterfly ----
        float g0[RL], g1[RL];
        #pragma unroll
        for (int r = 0; r < RL; ++r) {
            u64 v10 = mul2(s1p[r][0], tf[r][0]);
            u64 v11 = mul2(s1p[r][1], tf[r][1]);
            u64 g0p = fma2(v11, w1apk[1], mul2(v10, w1apk[0]));
            u64 g1p = fma2(v11, w1bpk[1], mul2(v10, w1bpk[0]));
            float a, b;
            unpack2(g0p, a, b); g0[r] = a + b;
            unpack2(g1p, a, b); g1[r] = a + b;
        }
        #pragma unroll
        for (int r = 0; r < RL; ++r) {
            u64 G = pack2(g0[r], g1[r]);            // reduce both together
            G = add2(G, shfl_xor64(G, 1));
            G = add2(G, shfl_xor64(G, 2));
            G = add2(G, shfl_xor64(G, 4));
            unpack2(G, g0[r], g1[r]);
        }

        if ((tid & 7) == 0)
            *(float4*)(out + (size_t)t * BB + gbase) =
                make_float4(g0[0], g0[1], g0[2], g0[3]);

        gam[0] = fmaf(hc[0], -g1[0], gam[0]);
        gam[1] = fmaf(hc[1], -g1[1], gam[1]);
        gam[2] = fmaf(hc[2], -g1[2], gam[2]);
        gam[3] = fmaf(hc[3], -g1[3], gam[3]);

        ec[0]=en4.x; ec[1]=en4.y; ec[2]=en4.z; ec[3]=en4.w;
        hc[0]=hn4.x; hc[1]=hn4.y; hc[2]=hn4.z; hc[3]=hn4.w;
    }
}

extern "C" void kernel_launch(void* const* d_in, const int* in_sizes, int n_in,
                              void* d_out, int out_size) {
    const float* eps = (const float*)d_in[0];
    const float* hs  = (const float*)d_in[1];
    const float* W1  = (const float*)d_in[2];
    const float* b1  = (const float*)d_in[3];
    const float* W2  = (const float*)d_in[4];
    const float* b2  = (const float*)d_in[5];
    const float* W3  = (const float*)d_in[6];
    float* out = (float*)d_out;

    // 16384 lanes / 128 per CTA = 128 CTAs x 256 threads
    // -> 32768 threads, 2 warps/SMSP on 128 SMs, split-K over 2 threads
    rnncell_sk_kernel<<<BB / LPC, BLK>>>(eps, hs, W1, b1, W2, b2, W3, out);
}